// round 1
// baseline (speedup 1.0000x reference)
#include <cuda_runtime.h>

// LIF scan: v' = step(v, I) with exact replication of the reference float ops:
//   v_euler = v + ((-v + 3000*I) / 150) * 0.01     (each op individually RN-rounded)
//   v_new = (v >= 15) ? 0 : v_euler
//   v_new = (v_new >= 15) ? 30 : v_new
//
// Invariant: entering any step, v is either exactly 30 (prior spike clamp) or < 15.
// Hence next step's reset predicate == this step's spike predicate, carried in a bool.

#define UNROLL_T 8
#define T_STEPS 1000
#define N_NEUR 131072
#define N2 (N_NEUR / 2)  // float2 pairs per timestep

__device__ __forceinline__ void lif_step(float& v, bool& p, float I) {
    // RN(1/150) as a float constant (correctly-rounded reciprocal)
    const float y = (float)(1.0 / 150.0);
    // num = (-v) + RN(3000*I)   (separate mul + add, matching XLA neg/mul/add)
    float pr  = __fmul_rn(I, 3000.0f);
    float num = __fadd_rn(pr, -v);
    // Correctly-rounded num/150 via Markstein refinement (== div.rn.f32)
    float q0  = __fmul_rn(num, y);
    float rr  = __fmaf_rn(q0, -150.0f, num);   // exact remainder via FMA
    float q   = __fmaf_rn(rr, y, q0);          // correctly rounded quotient
    // dv = q * 0.01 ; ve = v + dv  (separate roundings, as reference)
    float dv  = __fmul_rn(q, 0.01f);
    float ve  = __fadd_rn(v, dv);
    // selection logic (p == (v >= 15) entering this step)
    bool spike = (ve >= 15.0f) && (!p);        // FSETP.GE.AND
    float tv = p ? 0.0f : ve;                  // reset
    v = spike ? 30.0f : tv;                    // spike clamp
    p = spike;                                 // next step's reset predicate
}

__global__ void __launch_bounds__(64, 7)
lif_kernel_fixed(const float2* __restrict__ stim, float2* __restrict__ out) {
    const int idx = blockIdx.x * 64 + threadIdx.x;   // pair index, 0..N2-1 (grid covers exactly)
    const float2* __restrict__ sp = stim + idx;
    float2* __restrict__ op = out + idx;

    float v0 = 0.0f, v1 = 0.0f;
    bool p0 = false, p1 = false;

    const size_t row = (size_t)N2;                   // pairs per timestep (compile-time)
    const size_t chunk = (size_t)UNROLL_T * row;

    float2 buf[UNROLL_T];
    #pragma unroll
    for (int u = 0; u < UNROLL_T; u++) buf[u] = sp[(size_t)u * row];

    const float2* __restrict__ ld = sp + chunk;      // base of next chunk's loads
    float2* __restrict__ st = op;

    const int nchunks = T_STEPS / UNROLL_T;          // 125 (T divisible by 8)

    for (int c = 0; c < nchunks - 1; c++) {
        float2 nbuf[UNROLL_T];
        // Prefetch next chunk (8 independent LDG.64 in flight)
        #pragma unroll
        for (int u = 0; u < UNROLL_T; u++) nbuf[u] = ld[(size_t)u * row];
        // Compute + store current chunk
        #pragma unroll
        for (int u = 0; u < UNROLL_T; u++) {
            lif_step(v0, p0, buf[u].x);
            lif_step(v1, p1, buf[u].y);
            st[(size_t)u * row] = make_float2(v0, v1);
        }
        #pragma unroll
        for (int u = 0; u < UNROLL_T; u++) buf[u] = nbuf[u];
        ld += chunk;
        st += chunk;
    }
    // Final chunk (no prefetch)
    #pragma unroll
    for (int u = 0; u < UNROLL_T; u++) {
        lif_step(v0, p0, buf[u].x);
        lif_step(v1, p1, buf[u].y);
        st[(size_t)u * row] = make_float2(v0, v1);
    }
}

// Generic fallback (any N even/odd, T derived) — correctness-only path.
__global__ void lif_kernel_generic(const float* __restrict__ stim,
                                   float* __restrict__ out, int N, int T) {
    int n = blockIdx.x * blockDim.x + threadIdx.x;
    if (n >= N) return;
    float v = 0.0f;
    bool p = false;
    for (int t = 0; t < T; t++) {
        lif_step(v, p, stim[(size_t)t * N + n]);
        out[(size_t)t * N + n] = v;
    }
}

extern "C" void kernel_launch(void* const* d_in, const int* in_sizes, int n_in,
                              void* d_out, int out_size) {
    const float* stim = (const float*)d_in[0];
    float* out = (float*)d_out;

    if (in_sizes[0] == T_STEPS * N_NEUR && out_size == T_STEPS * N_NEUR) {
        // 65536 pairs / 64 threads = 1024 blocks (99% wave utilization on 148 SMs)
        lif_kernel_fixed<<<N2 / 64, 64>>>((const float2*)stim, (float2*)out);
    } else {
        // Fallback: assume T=1000 scan length, derive N
        int T = 1000;
        int N = in_sizes[0] / T;
        int threads = 128;
        int blocks = (N + threads - 1) / threads;
        lif_kernel_generic<<<blocks, threads>>>(stim, out, N, T);
    }
}